// round 14
// baseline (speedup 1.0000x reference)
#include <cuda_runtime.h>
#include <cuda_bf16.h>
#include <math.h>

// Problem shape (fixed by dataset)
#define NB   8
#define NC   128
#define NHW  1024
#define NTOT (NB*NHW)      // 8192
#define NCLS 5
// student scale = (1/T) * log2(e): epilogue is bare ex2.approx
#define S_SCALE (10.0f * 1.4426950408889634f)
#define LN2 0.6931471805599453f

#define BM 128             // i-rows per block
#define BN 128             // j-cols per tile
#define NQ 16              // j-sixteenths: grid = 64 i-tiles * 16 = 1024 blocks
#define NT 4               // j-tiles per block

// dynamic smem (bytes): A shared + per-warp private B slice + reduce area
#define SM_A    0                      // 32768
#define SM_BW   32768                  // 8 warps x 8192 private slice
#define SM_RED  (32768 + 8*8192)       // 98304, 2048 bytes
#define SMEM_TOTAL (98304 + 2048)      // 100352 -> 2 blocks/SM

// ---------------- device scratch (no allocations allowed) ----------------
__device__ __nv_bfloat16 g_sh[NTOT*NC];   // student bf16 (*S_SCALE)
__device__ __nv_bfloat16 g_th[NTOT*NC];   // teacher bf16
__device__ float g_sep[NQ*NTOT];          // partial sum-of-exp (sixteenth, i); single writer
__device__ float g_clsum[NCLS*NC];
__device__ float g_clcnt[NCLS];
__device__ float g_acc[2];
__device__ int   g_done;
__device__ int   g_lmode;

// ---------------- helpers ----------------
__device__ __forceinline__ void cpasync16(unsigned smem, const void* g) {
    asm volatile("cp.async.cg.shared.global [%0], [%1], 16;\n" :: "r"(smem), "l"(g));
}
__device__ __forceinline__ void cpcommit() {
    asm volatile("cp.async.commit_group;\n" ::: "memory");
}
template<int N> __device__ __forceinline__ void cpwait() {
    asm volatile("cp.async.wait_group %0;\n" :: "n"(N) : "memory");
}
__device__ __forceinline__ int get_label(const void* p, int i) {
    if (g_lmode) return (int)(((const long long*)p)[i]);
    return ((const int*)p)[i];
}
__device__ __forceinline__ void ldsm4(unsigned* r, unsigned addr) {
    asm volatile("ldmatrix.sync.aligned.m8n8.x4.shared.b16 {%0,%1,%2,%3}, [%4];"
                 : "=r"(r[0]), "=r"(r[1]), "=r"(r[2]), "=r"(r[3]) : "r"(addr));
}
__device__ __forceinline__ void mma16816(float* c, const unsigned* a, unsigned b0, unsigned b1) {
    asm volatile("mma.sync.aligned.m16n8k16.row.col.f32.bf16.bf16.f32 "
                 "{%0,%1,%2,%3}, {%4,%5,%6,%7}, {%8,%9}, {%0,%1,%2,%3};"
                 : "+f"(c[0]), "+f"(c[1]), "+f"(c[2]), "+f"(c[3])
                 : "r"(a[0]), "r"(a[1]), "r"(a[2]), "r"(a[3]), "r"(b0), "r"(b1));
}
__device__ __forceinline__ float ex2f(float x) {
    float y; asm("ex2.approx.f32 %0, %1;" : "=f"(y) : "f"(x)); return y;
}

// Cooperative: one 128x128 bf16 tile into SMEM (swizzle c' = c ^ (row & 7)).
__device__ __forceinline__ void load_tile(unsigned dst, const __nv_bfloat16* src, int tid) {
    #pragma unroll
    for (int it = 0; it < 8; it++) {
        int idx = tid + it * 256;
        int row = idx >> 4, c = idx & 15;
        unsigned off = (unsigned)(row * 256 + ((c ^ (row & 7)) << 4));
        cpasync16(dst + off, (const char*)src + row * 256 + c * 16);
    }
}
// Per-warp: 32x128 bf16 slice (32 rows x 256B), same swizzle, 16 chunks/lane.
__device__ __forceinline__ void load_bslice(unsigned dst, const __nv_bfloat16* src, int lane) {
    #pragma unroll
    for (int it = 0; it < 16; it++) {
        int idx = lane + it * 32;
        int row = idx >> 4, c = idx & 15;
        unsigned off = (unsigned)(row * 256 + ((c ^ (row & 7)) << 4));
        cpasync16(dst + off, (const char*)src + row * 256 + c * 16);
    }
}

// ---------------- K0: label dtype probe + zero accumulators ----------------
__global__ void k_init(const int* sl, const int* tl) {
    int t = threadIdx.x;
    if (t == 0) {
        int allzero = 1;
        for (int i = 1; i < 256; i += 2)
            if (sl[i] != 0 || tl[i] != 0) { allzero = 0; break; }
        g_lmode = allzero;   // int64 labels 0..4 -> all odd 32-bit words zero
        g_done = 0;
    }
    if (t < NCLS*NC) g_clsum[t] = 0.f;
    if (t < NCLS)    g_clcnt[t] = 0.f;
    if (t < 2)       g_acc[t]   = 0.f;
}

// ---------------- K1: normalize + transpose + bf16 (+ teacher class sums) ----------------
__global__ __launch_bounds__(256) void k_norm(const float* __restrict__ s_in,
                                              const float* __restrict__ t_in,
                                              const void* __restrict__ tl) {
    __shared__ float sh[NC][33];
    __shared__ float part[8][32];
    __shared__ float invn[32];
    __shared__ float cls[NCLS][NC];
    __shared__ int lbls[32];
    int stu = (blockIdx.y == 0);
    const float* in   = stu ? s_in : t_in;
    __nv_bfloat16* outh = stu ? g_sh : g_th;
    const float scale = stu ? S_SCALE : 1.0f;
    int b   = blockIdx.x >> 5;
    int hw0 = (blockIdx.x & 31) << 5;
    int n0  = b * NHW + hw0;
    int tx = threadIdx.x & 31, ty = threadIdx.x >> 5;

    if (!stu) {
        for (int q = threadIdx.x; q < NCLS*NC; q += 256) ((float*)cls)[q] = 0.f;
        if (threadIdx.x < 32) {
            int l = get_label(tl, n0 + threadIdx.x);
            lbls[threadIdx.x] = min(max(l, 0), NCLS - 1);
        }
    }

    float p = 0.f;
    const float* base = in + (size_t)b * NC * NHW + hw0 + tx;
    #pragma unroll
    for (int c0 = 0; c0 < NC; c0 += 8) {
        float v = base[(size_t)(c0 + ty) * NHW];
        sh[c0 + ty][tx] = v;
        p += v * v;
    }
    part[ty][tx] = p;
    __syncthreads();
    if (ty == 0) {
        float s = 0.f;
        #pragma unroll
        for (int q = 0; q < 8; q++) s += part[q][tx];
        invn[tx] = rsqrtf(s) * scale;
    }
    __syncthreads();
    for (int idx = threadIdx.x; idx < NC * 32; idx += 256) {
        int c = idx & 127, q = idx >> 7;
        float v = sh[c][q] * invn[q];
        size_t o = (size_t)(n0 + q) * NC + c;
        outh[o] = __float2bfloat16(v);
        if (!stu) atomicAdd(&cls[lbls[q]][c], v);
    }
    if (!stu) {
        __syncthreads();
        for (int q = threadIdx.x; q < NCLS*NC; q += 256)
            atomicAdd(&g_clsum[q], ((float*)cls)[q]);
        if (threadIdx.x < 32)
            atomicAdd(&g_clcnt[lbls[threadIdx.x]], 1.f);
    }
}

// ---------------- K2: barrier-free warp-autonomous bf16 GEMM + exp2 ----------------
// (unchanged from R13 pass — near the legacy-HMMA pipe floor)
extern __shared__ char smem_raw[];

__global__ __launch_bounds__(256, 2) void k_main() {
    unsigned sbase = (unsigned)__cvta_generic_to_shared(smem_raw);
    int tid = threadIdx.x, lane = tid & 31, wid = tid >> 5;
    int i0    = (blockIdx.x >> 4) * BM;
    int jq    = blockIdx.x & 15;
    int jbase = jq * (NTOT / NQ);          // 512-wide j range
    int wr = wid & 1, wc = wid >> 1;
    int m_base = wr * 64, n_base = wc * 32;
    int sub = lane >> 3, l7 = lane & 7;
    unsigned mybuf = sbase + SM_BW + wid * 8192;

    unsigned a_rel[4]; int a_sw[4];
    #pragma unroll
    for (int mf = 0; mf < 4; mf++) {
        int row = m_base + mf * 16 + (sub & 1) * 8 + l7;
        a_rel[mf] = row * 256; a_sw[mf] = row & 7;
    }
    const int a_co = sub >> 1;
    unsigned b_rel[2]; int b_sw[2];
    #pragma unroll
    for (int p = 0; p < 2; p++) {
        int row = p * 16 + (sub >> 1) * 8 + l7;   // local row within slice
        b_rel[p] = row * 256; b_sw[p] = row & 7;
    }
    const int b_co = sub & 1;

    // prologue: A (cooperative) + own slice for tile 0, one group
    load_tile(sbase + SM_A, g_sh + (size_t)i0 * NC, tid);
    load_bslice(mybuf, g_th + (size_t)(jbase + n_base) * NC, lane);
    cpcommit();
    cpwait<0>();
    __syncthreads();      // A visible to all warps; only barrier before epilogue

    float rs[8];
    #pragma unroll
    for (int q = 0; q < 8; q++) rs[q] = 0.f;
    unsigned Ah = sbase + SM_A;

    #pragma unroll 1
    for (int jt = 0; jt < NT; jt++) {
        if (jt > 0) cpwait<0>();   // own prefetch done (latency hidden by prior ex2)

        float c[4][4][4];
        #pragma unroll
        for (int mf = 0; mf < 4; mf++)
            #pragma unroll
            for (int nf = 0; nf < 4; nf++)
                #pragma unroll
                for (int q = 0; q < 4; q++) c[mf][nf][q] = 0.f;

        #pragma unroll
        for (int ks = 0; ks < 8; ks++) {
            unsigned ah[4][4], bh[2][4];
            #pragma unroll
            for (int mf = 0; mf < 4; mf++)
                ldsm4(ah[mf], Ah + a_rel[mf] + (((2*ks + a_co) ^ a_sw[mf]) << 4));
            #pragma unroll
            for (int p = 0; p < 2; p++)
                ldsm4(bh[p], mybuf + b_rel[p] + (((2*ks + b_co) ^ b_sw[p]) << 4));
            #pragma unroll
            for (int mf = 0; mf < 4; mf++) {
                mma16816(c[mf][0], ah[mf], bh[0][0], bh[0][1]);
                mma16816(c[mf][1], ah[mf], bh[0][2], bh[0][3]);
                mma16816(c[mf][2], ah[mf], bh[1][0], bh[1][1]);
                mma16816(c[mf][3], ah[mf], bh[1][2], bh[1][3]);
            }
        }
        // prefetch next tile's slice (lands while ex2 burst runs)
        if (jt + 1 < NT) {
            load_bslice(mybuf, g_th + (size_t)(jbase + (jt+1)*BN + n_base) * NC, lane);
            cpcommit();
        }
        // 2^y accumulate (y = logit*log2e, |y|<=14.5 -> fp32 safe; no max pass)
        #pragma unroll
        for (int mf = 0; mf < 4; mf++) {
            float e0 = 0.f, e1 = 0.f;
            #pragma unroll
            for (int nf = 0; nf < 4; nf++) {
                e0 += ex2f(c[mf][nf][0]) + ex2f(c[mf][nf][1]);
                e1 += ex2f(c[mf][nf][2]) + ex2f(c[mf][nf][3]);
            }
            rs[mf*2]   += e0;   // row = m_base + mf*16 + lane/4
            rs[mf*2+1] += e1;   // row = m_base + mf*16 + lane/4 + 8
        }
    }

    // epilogue reduction (separate SMEM region; one barrier)
    float* red = (float*)(smem_raw + SM_RED);   // [128][4]
    #pragma unroll
    for (int q = 0; q < 8; q++) {
        rs[q] += __shfl_xor_sync(0xFFFFFFFFu, rs[q], 1);
        rs[q] += __shfl_xor_sync(0xFFFFFFFFu, rs[q], 2);
    }
    if ((lane & 3) == 0) {
        int r0 = m_base + (lane >> 2);
        #pragma unroll
        for (int mf = 0; mf < 4; mf++) {
            red[(r0 + mf*16    ) * 4 + wc] = rs[mf*2];
            red[(r0 + mf*16 + 8) * 4 + wc] = rs[mf*2+1];
        }
    }
    __syncthreads();
    if (tid < BM) {
        float s = red[tid*4] + red[tid*4+1] + red[tid*4+2] + red[tid*4+3];
        g_sep[jq * NTOT + i0 + tid] = s;   // single writer: deterministic
    }
}

// ---------------- K3: thread-per-row anchor terms (no shuffles) + loss ----------------
// grid = 128 blocks x 64 threads: ~128 SMs active, each thread owns one row.
// dot = 32 private chunk-FMAs (bf16 student x fp32 clsum); sep = 16 coalesced
// loads (consecutive threads -> consecutive rows). Zero shuffle chains.
__global__ __launch_bounds__(64) void k_final(const void* sl, float* out) {
    int row = blockIdx.x * 64 + threadIdx.x;
    int lbl = get_label(sl, row);
    int lc = min(max(lbl, 0), NCLS - 1);

    const uint2*  sv = (const uint2*)(g_sh + (size_t)row * NC);
    const float4* cv = (const float4*)(g_clsum + lc * NC);
    float dot = 0.f;
    #pragma unroll
    for (int q = 0; q < 32; q++) {
        uint2 u = sv[q];
        float4 b = cv[q];
        __nv_bfloat162 p0 = *(__nv_bfloat162*)&u.x;
        __nv_bfloat162 p1 = *(__nv_bfloat162*)&u.y;
        dot += __bfloat162float(p0.x)*b.x + __bfloat162float(p0.y)*b.y
             + __bfloat162float(p1.x)*b.z + __bfloat162float(p1.y)*b.w;
    }

    float sep = 0.f;
    #pragma unroll
    for (int q = 0; q < NQ; q++) sep += g_sep[q * NTOT + row];

    float cnt = g_clcnt[lc];
    float lse = logf(sep);                      // ln of sum 2^y = sum e^logit
    float mlpp = (dot * LN2 - cnt * lse) / (cnt + 1e-8f);
    float w = (cnt > 1e-8f && lbl != 0) ? 1.f : 0.f;

    __shared__ float r1[64], r2[64];
    r1[threadIdx.x] = w * mlpp;
    r2[threadIdx.x] = w;
    __syncthreads();
    for (int s = 32; s > 0; s >>= 1) {
        if (threadIdx.x < s) {
            r1[threadIdx.x] += r1[threadIdx.x + s];
            r2[threadIdx.x] += r2[threadIdx.x + s];
        }
        __syncthreads();
    }
    if (threadIdx.x == 0) {
        atomicAdd(&g_acc[0], r1[0]);
        atomicAdd(&g_acc[1], r2[0]);
        __threadfence();
        if (atomicAdd(&g_done, 1) == (int)gridDim.x - 1) {
            __threadfence();
            out[0] = -g_acc[0] / g_acc[1];
        }
    }
}

// ---------------- launch ----------------
extern "C" void kernel_launch(void* const* d_in, const int* in_sizes, int n_in,
                              void* d_out, int out_size) {
    const float* s_in = (const float*)d_in[0];
    const float* t_in = (const float*)d_in[1];
    const void*  sl   = d_in[2];
    const void*  tl   = d_in[3];
    float* out = (float*)d_out;

    cudaFuncSetAttribute(k_main, cudaFuncAttributeMaxDynamicSharedMemorySize, SMEM_TOTAL);

    k_init<<<1, 640>>>((const int*)sl, (const int*)tl);
    k_norm<<<dim3(256, 2), 256>>>(s_in, t_in, tl);
    k_main<<<(NTOT / BM) * NQ, 256, SMEM_TOTAL>>>();
    k_final<<<NTOT / 64, 64>>>(sl, out);
}

// round 15
// speedup vs baseline: 1.0593x; 1.0593x over previous
#include <cuda_runtime.h>
#include <cuda_bf16.h>
#include <math.h>

// Problem shape (fixed by dataset)
#define NB   8
#define NC   128
#define NHW  1024
#define NTOT (NB*NHW)      // 8192
#define NCLS 5
// student scale = (1/T) * log2(e): epilogue is bare ex2.approx
#define S_SCALE (10.0f * 1.4426950408889634f)
#define LN2 0.6931471805599453f

#define BM 128             // i-rows per block
#define BN 128             // j-cols per tile
#define NQ 16              // j-sixteenths: grid = 64 i-tiles * 16 = 1024 blocks
#define NT 4               // j-tiles per block

// dynamic smem (bytes): A shared + per-warp private B slice + reduce area
#define SM_A    0                      // 32768
#define SM_BW   32768                  // 8 warps x 8192 private slice
#define SM_RED  (32768 + 8*8192)       // 98304, 2048 bytes
#define SMEM_TOTAL (98304 + 2048)      // 100352 -> 2 blocks/SM

// ---------------- device scratch (no allocations allowed) ----------------
__device__ __nv_bfloat16 g_sh[NTOT*NC];   // student bf16 (*S_SCALE)
__device__ __nv_bfloat16 g_th[NTOT*NC];   // teacher bf16
__device__ float g_sep[NQ*NTOT];          // partial sum-of-exp (sixteenth, i); single writer
__device__ float g_clsum[NCLS*NC];
__device__ float g_clcnt[NCLS];
__device__ float g_acc[2];
__device__ int   g_done;
__device__ int   g_lmode;

// ---------------- helpers ----------------
__device__ __forceinline__ void cpasync16(unsigned smem, const void* g) {
    asm volatile("cp.async.cg.shared.global [%0], [%1], 16;\n" :: "r"(smem), "l"(g));
}
__device__ __forceinline__ void cpcommit() {
    asm volatile("cp.async.commit_group;\n" ::: "memory");
}
template<int N> __device__ __forceinline__ void cpwait() {
    asm volatile("cp.async.wait_group %0;\n" :: "n"(N) : "memory");
}
__device__ __forceinline__ int get_label(const void* p, int i) {
    if (g_lmode) return (int)(((const long long*)p)[i]);
    return ((const int*)p)[i];
}
__device__ __forceinline__ void ldsm4(unsigned* r, unsigned addr) {
    asm volatile("ldmatrix.sync.aligned.m8n8.x4.shared.b16 {%0,%1,%2,%3}, [%4];"
                 : "=r"(r[0]), "=r"(r[1]), "=r"(r[2]), "=r"(r[3]) : "r"(addr));
}
__device__ __forceinline__ void mma16816(float* c, const unsigned* a, unsigned b0, unsigned b1) {
    asm volatile("mma.sync.aligned.m16n8k16.row.col.f32.bf16.bf16.f32 "
                 "{%0,%1,%2,%3}, {%4,%5,%6,%7}, {%8,%9}, {%0,%1,%2,%3};"
                 : "+f"(c[0]), "+f"(c[1]), "+f"(c[2]), "+f"(c[3])
                 : "r"(a[0]), "r"(a[1]), "r"(a[2]), "r"(a[3]), "r"(b0), "r"(b1));
}
__device__ __forceinline__ float ex2f(float x) {
    float y; asm("ex2.approx.f32 %0, %1;" : "=f"(y) : "f"(x)); return y;
}

// Cooperative: one 128x128 bf16 tile into SMEM (swizzle c' = c ^ (row & 7)).
__device__ __forceinline__ void load_tile(unsigned dst, const __nv_bfloat16* src, int tid) {
    #pragma unroll
    for (int it = 0; it < 8; it++) {
        int idx = tid + it * 256;
        int row = idx >> 4, c = idx & 15;
        unsigned off = (unsigned)(row * 256 + ((c ^ (row & 7)) << 4));
        cpasync16(dst + off, (const char*)src + row * 256 + c * 16);
    }
}
// Per-warp: 32x128 bf16 slice (32 rows x 256B), same swizzle, 16 chunks/lane.
__device__ __forceinline__ void load_bslice(unsigned dst, const __nv_bfloat16* src, int lane) {
    #pragma unroll
    for (int it = 0; it < 16; it++) {
        int idx = lane + it * 32;
        int row = idx >> 4, c = idx & 15;
        unsigned off = (unsigned)(row * 256 + ((c ^ (row & 7)) << 4));
        cpasync16(dst + off, (const char*)src + row * 256 + c * 16);
    }
}

// ---------------- K0: label dtype probe + zero accumulators ----------------
__global__ void k_init(const int* sl, const int* tl) {
    int t = threadIdx.x;
    if (t == 0) {
        int allzero = 1;
        for (int i = 1; i < 256; i += 2)
            if (sl[i] != 0 || tl[i] != 0) { allzero = 0; break; }
        g_lmode = allzero;   // int64 labels 0..4 -> all odd 32-bit words zero
        g_done = 0;
    }
    if (t < NCLS*NC) g_clsum[t] = 0.f;
    if (t < NCLS)    g_clcnt[t] = 0.f;
    if (t < 2)       g_acc[t]   = 0.f;
}

// ---------------- K1: normalize + transpose + bf16 (+ teacher class sums) ----------------
__global__ __launch_bounds__(256) void k_norm(const float* __restrict__ s_in,
                                              const float* __restrict__ t_in,
                                              const void* __restrict__ tl) {
    __shared__ float sh[NC][33];
    __shared__ float part[8][32];
    __shared__ float invn[32];
    __shared__ float cls[NCLS][NC];
    __shared__ int lbls[32];
    int stu = (blockIdx.y == 0);
    const float* in   = stu ? s_in : t_in;
    __nv_bfloat16* outh = stu ? g_sh : g_th;
    const float scale = stu ? S_SCALE : 1.0f;
    int b   = blockIdx.x >> 5;
    int hw0 = (blockIdx.x & 31) << 5;
    int n0  = b * NHW + hw0;
    int tx = threadIdx.x & 31, ty = threadIdx.x >> 5;

    if (!stu) {
        for (int q = threadIdx.x; q < NCLS*NC; q += 256) ((float*)cls)[q] = 0.f;
        if (threadIdx.x < 32) {
            int l = get_label(tl, n0 + threadIdx.x);
            lbls[threadIdx.x] = min(max(l, 0), NCLS - 1);
        }
    }

    float p = 0.f;
    const float* base = in + (size_t)b * NC * NHW + hw0 + tx;
    #pragma unroll
    for (int c0 = 0; c0 < NC; c0 += 8) {
        float v = base[(size_t)(c0 + ty) * NHW];
        sh[c0 + ty][tx] = v;
        p += v * v;
    }
    part[ty][tx] = p;
    __syncthreads();
    if (ty == 0) {
        float s = 0.f;
        #pragma unroll
        for (int q = 0; q < 8; q++) s += part[q][tx];
        invn[tx] = rsqrtf(s) * scale;
    }
    __syncthreads();
    for (int idx = threadIdx.x; idx < NC * 32; idx += 256) {
        int c = idx & 127, q = idx >> 7;
        float v = sh[c][q] * invn[q];
        size_t o = (size_t)(n0 + q) * NC + c;
        outh[o] = __float2bfloat16(v);
        if (!stu) atomicAdd(&cls[lbls[q]][c], v);
    }
    if (!stu) {
        __syncthreads();
        for (int q = threadIdx.x; q < NCLS*NC; q += 256)
            atomicAdd(&g_clsum[q], ((float*)cls)[q]);
        if (threadIdx.x < 32)
            atomicAdd(&g_clcnt[lbls[threadIdx.x]], 1.f);
    }
}

// ---------------- K2: barrier-free warp-autonomous bf16 GEMM + exp2 ----------------
// (byte-identical to the R13 pass — near the legacy-HMMA pipe floor)
extern __shared__ char smem_raw[];

__global__ __launch_bounds__(256, 2) void k_main() {
    unsigned sbase = (unsigned)__cvta_generic_to_shared(smem_raw);
    int tid = threadIdx.x, lane = tid & 31, wid = tid >> 5;
    int i0    = (blockIdx.x >> 4) * BM;
    int jq    = blockIdx.x & 15;
    int jbase = jq * (NTOT / NQ);          // 512-wide j range
    int wr = wid & 1, wc = wid >> 1;
    int m_base = wr * 64, n_base = wc * 32;
    int sub = lane >> 3, l7 = lane & 7;
    unsigned mybuf = sbase + SM_BW + wid * 8192;

    unsigned a_rel[4]; int a_sw[4];
    #pragma unroll
    for (int mf = 0; mf < 4; mf++) {
        int row = m_base + mf * 16 + (sub & 1) * 8 + l7;
        a_rel[mf] = row * 256; a_sw[mf] = row & 7;
    }
    const int a_co = sub >> 1;
    unsigned b_rel[2]; int b_sw[2];
    #pragma unroll
    for (int p = 0; p < 2; p++) {
        int row = p * 16 + (sub >> 1) * 8 + l7;   // local row within slice
        b_rel[p] = row * 256; b_sw[p] = row & 7;
    }
    const int b_co = sub & 1;

    // prologue: A (cooperative) + own slice for tile 0, one group
    load_tile(sbase + SM_A, g_sh + (size_t)i0 * NC, tid);
    load_bslice(mybuf, g_th + (size_t)(jbase + n_base) * NC, lane);
    cpcommit();
    cpwait<0>();
    __syncthreads();      // A visible to all warps; only barrier before epilogue

    float rs[8];
    #pragma unroll
    for (int q = 0; q < 8; q++) rs[q] = 0.f;
    unsigned Ah = sbase + SM_A;

    #pragma unroll 1
    for (int jt = 0; jt < NT; jt++) {
        if (jt > 0) cpwait<0>();   // own prefetch done (latency hidden by prior ex2)

        float c[4][4][4];
        #pragma unroll
        for (int mf = 0; mf < 4; mf++)
            #pragma unroll
            for (int nf = 0; nf < 4; nf++)
                #pragma unroll
                for (int q = 0; q < 4; q++) c[mf][nf][q] = 0.f;

        #pragma unroll
        for (int ks = 0; ks < 8; ks++) {
            unsigned ah[4][4], bh[2][4];
            #pragma unroll
            for (int mf = 0; mf < 4; mf++)
                ldsm4(ah[mf], Ah + a_rel[mf] + (((2*ks + a_co) ^ a_sw[mf]) << 4));
            #pragma unroll
            for (int p = 0; p < 2; p++)
                ldsm4(bh[p], mybuf + b_rel[p] + (((2*ks + b_co) ^ b_sw[p]) << 4));
            #pragma unroll
            for (int mf = 0; mf < 4; mf++) {
                mma16816(c[mf][0], ah[mf], bh[0][0], bh[0][1]);
                mma16816(c[mf][1], ah[mf], bh[0][2], bh[0][3]);
                mma16816(c[mf][2], ah[mf], bh[1][0], bh[1][1]);
                mma16816(c[mf][3], ah[mf], bh[1][2], bh[1][3]);
            }
        }
        // prefetch next tile's slice (lands while ex2 burst runs)
        if (jt + 1 < NT) {
            load_bslice(mybuf, g_th + (size_t)(jbase + (jt+1)*BN + n_base) * NC, lane);
            cpcommit();
        }
        // 2^y accumulate (y = logit*log2e, |y|<=14.5 -> fp32 safe; no max pass)
        #pragma unroll
        for (int mf = 0; mf < 4; mf++) {
            float e0 = 0.f, e1 = 0.f;
            #pragma unroll
            for (int nf = 0; nf < 4; nf++) {
                e0 += ex2f(c[mf][nf][0]) + ex2f(c[mf][nf][1]);
                e1 += ex2f(c[mf][nf][2]) + ex2f(c[mf][nf][3]);
            }
            rs[mf*2]   += e0;   // row = m_base + mf*16 + lane/4
            rs[mf*2+1] += e1;   // row = m_base + mf*16 + lane/4 + 8
        }
    }

    // epilogue reduction (separate SMEM region; one barrier)
    float* red = (float*)(smem_raw + SM_RED);   // [128][4]
    #pragma unroll
    for (int q = 0; q < 8; q++) {
        rs[q] += __shfl_xor_sync(0xFFFFFFFFu, rs[q], 1);
        rs[q] += __shfl_xor_sync(0xFFFFFFFFu, rs[q], 2);
    }
    if ((lane & 3) == 0) {
        int r0 = m_base + (lane >> 2);
        #pragma unroll
        for (int mf = 0; mf < 4; mf++) {
            red[(r0 + mf*16    ) * 4 + wc] = rs[mf*2];
            red[(r0 + mf*16 + 8) * 4 + wc] = rs[mf*2+1];
        }
    }
    __syncthreads();
    if (tid < BM) {
        float s = red[tid*4] + red[tid*4+1] + red[tid*4+2] + red[tid*4+3];
        g_sep[jq * NTOT + i0 + tid] = s;   // single writer: deterministic
    }
}

// ---------------- K3: quad-per-row anchor terms + loss ----------------
// 4 threads per row: 8 dot chunks + 4 sep partials each, reduced with TWO
// shfl_xor steps (stay inside the quad). 128 blocks x 256 threads = 32K
// threads -> high occupancy (R14's 64-thr blocks were latency-starved).
__global__ __launch_bounds__(256) void k_final(const void* sl, float* out) {
    int tid = threadIdx.x;
    int qt = tid & 3;                       // quad lane
    int row = blockIdx.x * 64 + (tid >> 2); // 64 rows per block
    int lbl = get_label(sl, row);
    int lc = min(max(lbl, 0), NCLS - 1);

    const uint2*  sv = (const uint2*)(g_sh + (size_t)row * NC) + qt * 8;
    const float4* cv = (const float4*)(g_clsum + lc * NC) + qt * 8;
    float dot = 0.f;
    #pragma unroll
    for (int q = 0; q < 8; q++) {
        uint2 u = sv[q];
        float4 b = cv[q];
        __nv_bfloat162 p0 = *(__nv_bfloat162*)&u.x;
        __nv_bfloat162 p1 = *(__nv_bfloat162*)&u.y;
        dot += __bfloat162float(p0.x)*b.x + __bfloat162float(p0.y)*b.y
             + __bfloat162float(p1.x)*b.z + __bfloat162float(p1.y)*b.w;
    }
    float sep = 0.f;
    #pragma unroll
    for (int q = 0; q < 4; q++) sep += g_sep[(qt * 4 + q) * NTOT + row];

    dot += __shfl_xor_sync(0xFFFFFFFFu, dot, 1);
    dot += __shfl_xor_sync(0xFFFFFFFFu, dot, 2);
    sep += __shfl_xor_sync(0xFFFFFFFFu, sep, 1);
    sep += __shfl_xor_sync(0xFFFFFFFFu, sep, 2);

    __shared__ float r1[64], r2[64];
    if (qt == 0) {
        float cnt = g_clcnt[lc];
        float lse = logf(sep);              // ln of sum 2^y = sum e^logit
        float mlpp = (dot * LN2 - cnt * lse) / (cnt + 1e-8f);
        float w = (cnt > 1e-8f && lbl != 0) ? 1.f : 0.f;
        r1[tid >> 2] = w * mlpp;
        r2[tid >> 2] = w;
    }
    __syncthreads();
    if (tid < 32) {
        float s1 = r1[tid] + r1[tid + 32];
        float s2 = r2[tid] + r2[tid + 32];
        #pragma unroll
        for (int o = 16; o > 0; o >>= 1) {
            s1 += __shfl_xor_sync(0xFFFFFFFFu, s1, o);
            s2 += __shfl_xor_sync(0xFFFFFFFFu, s2, o);
        }
        if (tid == 0) {
            atomicAdd(&g_acc[0], s1);
            atomicAdd(&g_acc[1], s2);
            __threadfence();
            if (atomicAdd(&g_done, 1) == (int)gridDim.x - 1) {
                __threadfence();
                out[0] = -g_acc[0] / g_acc[1];
            }
        }
    }
}

// ---------------- launch ----------------
extern "C" void kernel_launch(void* const* d_in, const int* in_sizes, int n_in,
                              void* d_out, int out_size) {
    const float* s_in = (const float*)d_in[0];
    const float* t_in = (const float*)d_in[1];
    const void*  sl   = d_in[2];
    const void*  tl   = d_in[3];
    float* out = (float*)d_out;

    cudaFuncSetAttribute(k_main, cudaFuncAttributeMaxDynamicSharedMemorySize, SMEM_TOTAL);

    k_init<<<1, 640>>>((const int*)sl, (const int*)tl);
    k_norm<<<dim3(256, 2), 256>>>(s_in, t_in, tl);
    k_main<<<(NTOT / BM) * NQ, 256, SMEM_TOTAL>>>();
    k_final<<<NTOT / 64, 256>>>(sl, out);
}